// round 7
// baseline (speedup 1.0000x reference)
#include <cuda_runtime.h>
#include <cuda_bf16.h>
#include <cuda_fp8.h>
#include <math.h>
#include <stdint.h>

// ---------------- problem constants ----------------
#define NTOK 16384      // 8 * 2048 tokens
#define SEQ  2048
#define BATCH 8
#define DIMC 384
#define QKV3 1152
#define HID  1536
#define HEADS 6
#define HDIM 64
#define EPSV 1e-5f

// ---------------- scratch (device globals) ----------------
__device__ __nv_bfloat16 g_hb  [(size_t)NTOK * DIMC];   // LN1 out (bf16)
__device__ uint8_t       g_h8  [(size_t)NTOK * DIMC];   // LN2 out (fp8)
__device__ __nv_bfloat16 g_qkvb[(size_t)NTOK * QKV3];
__device__ __nv_bfloat16 g_ob  [(size_t)NTOK * DIMC];
__device__ uint8_t       g_a8  [(size_t)NTOK * HID];    // fc1 out (fp8)
__device__ uint8_t       g_b8  [(size_t)NTOK * HID];    // eye1 out (fp8)
__device__ __nv_bfloat16 g_ab  [(size_t)NTOK * HID];    // eye2 out (bf16)
__device__ __nv_bfloat16 g_wqkv [(size_t)QKV3 * DIMC];
__device__ __nv_bfloat16 g_wproj[(size_t)DIMC * DIMC];
__device__ __nv_bfloat16 g_wfc2 [(size_t)DIMC * HID];
__device__ uint8_t       g_wfc1_8 [(size_t)HID * DIMC];
__device__ uint8_t       g_weye1_8[(size_t)HID * HID];
__device__ uint8_t       g_weye2_8[(size_t)HID * HID];

// ---------------- helpers ----------------
__device__ __forceinline__ uint32_t smem_u32(const void* p) {
    return (uint32_t)__cvta_generic_to_shared(p);
}
__device__ __forceinline__ void ldm_x4(uint32_t& r0, uint32_t& r1, uint32_t& r2, uint32_t& r3, uint32_t a) {
    asm volatile("ldmatrix.sync.aligned.m8n8.x4.shared.b16 {%0,%1,%2,%3},[%4];\n"
                 : "=r"(r0), "=r"(r1), "=r"(r2), "=r"(r3) : "r"(a));
}
__device__ __forceinline__ void ldm_x4_t(uint32_t& r0, uint32_t& r1, uint32_t& r2, uint32_t& r3, uint32_t a) {
    asm volatile("ldmatrix.sync.aligned.m8n8.x4.trans.shared.b16 {%0,%1,%2,%3},[%4];\n"
                 : "=r"(r0), "=r"(r1), "=r"(r2), "=r"(r3) : "r"(a));
}
__device__ __forceinline__ void mma_bf16(float c[4], const uint32_t a[4], const uint32_t b[2]) {
    asm volatile(
        "mma.sync.aligned.m16n8k16.row.col.f32.bf16.bf16.f32 "
        "{%0,%1,%2,%3},{%4,%5,%6,%7},{%8,%9},{%0,%1,%2,%3};\n"
        : "+f"(c[0]), "+f"(c[1]), "+f"(c[2]), "+f"(c[3])
        : "r"(a[0]), "r"(a[1]), "r"(a[2]), "r"(a[3]), "r"(b[0]), "r"(b[1]));
}
__device__ __forceinline__ void mma_fp8(float c[4], const uint32_t a[4], const uint32_t b[2]) {
    asm volatile(
        "mma.sync.aligned.m16n8k32.row.col.f32.e4m3.e4m3.f32 "
        "{%0,%1,%2,%3},{%4,%5,%6,%7},{%8,%9},{%0,%1,%2,%3};\n"
        : "+f"(c[0]), "+f"(c[1]), "+f"(c[2]), "+f"(c[3])
        : "r"(a[0]), "r"(a[1]), "r"(a[2]), "r"(a[3]), "r"(b[0]), "r"(b[1]));
}
__device__ __forceinline__ uint32_t packbf(float lo, float hi) {
    __nv_bfloat162 h = __floats2bfloat162_rn(lo, hi);
    return *reinterpret_cast<uint32_t*>(&h);
}
__device__ __forceinline__ uint16_t packf8(float lo, float hi) {
    return (uint16_t)__nv_cvt_float2_to_fp8x2(make_float2(lo, hi), __NV_SATFINITE, __NV_E4M3);
}
__device__ __forceinline__ float gelu_exact(float x) {
    return 0.5f * x * (1.0f + erff(x * 0.7071067811865475f));
}

// ---------------- weight converts ----------------
__global__ void f2bf_kernel(const float* __restrict__ in, __nv_bfloat16* __restrict__ out, int n) {
    int i = (blockIdx.x * blockDim.x + threadIdx.x) * 4;
    if (i < n) {
        float4 v = *(const float4*)(in + i);
        *(__nv_bfloat162*)(out + i)     = __floats2bfloat162_rn(v.x, v.y);
        *(__nv_bfloat162*)(out + i + 2) = __floats2bfloat162_rn(v.z, v.w);
    }
}
__global__ void f2f8_kernel(const float* __restrict__ in, uint8_t* __restrict__ out, int n) {
    int i = (blockIdx.x * blockDim.x + threadIdx.x) * 4;
    if (i < n) {
        float4 v = *(const float4*)(in + i);
        uint32_t lo = packf8(v.x, v.y);
        uint32_t hi = packf8(v.z, v.w);
        *(uint32_t*)(out + i) = lo | (hi << 16);
    }
}

// ---------------- LayerNorm ----------------
template<int OUT8>
__global__ void ln_kernel(const float* __restrict__ x, const float* __restrict__ w,
                          const float* __restrict__ b, void* __restrict__ outp)
{
    const int t = blockIdx.x;
    const float* xr = x + (size_t)t * DIMC;
    const int tid = threadIdx.x;

    float v0 = xr[tid], v1 = xr[tid + 128], v2 = xr[tid + 256];
    float s = v0 + v1 + v2;
    float q = v0 * v0 + v1 * v1 + v2 * v2;
    #pragma unroll
    for (int off = 16; off > 0; off >>= 1) {
        s += __shfl_xor_sync(0xffffffffu, s, off);
        q += __shfl_xor_sync(0xffffffffu, q, off);
    }
    __shared__ float ss[4], qq[4];
    if ((tid & 31) == 0) { ss[tid >> 5] = s; qq[tid >> 5] = q; }
    __syncthreads();
    s = ss[0] + ss[1] + ss[2] + ss[3];
    q = qq[0] + qq[1] + qq[2] + qq[3];
    const float mean = s * (1.0f / DIMC);
    const float var  = q * (1.0f / DIMC) - mean * mean;
    const float inv  = rsqrtf(var + EPSV);

    const float r0 = (v0 - mean) * inv * w[tid]       + b[tid];
    const float r1 = (v1 - mean) * inv * w[tid + 128] + b[tid + 128];
    const float r2 = (v2 - mean) * inv * w[tid + 256] + b[tid + 256];
    if (OUT8) {
        uint8_t* orow = (uint8_t*)outp + (size_t)t * DIMC;
        orow[tid]       = (uint8_t)__nv_cvt_float_to_fp8(r0, __NV_SATFINITE, __NV_E4M3);
        orow[tid + 128] = (uint8_t)__nv_cvt_float_to_fp8(r1, __NV_SATFINITE, __NV_E4M3);
        orow[tid + 256] = (uint8_t)__nv_cvt_float_to_fp8(r2, __NV_SATFINITE, __NV_E4M3);
    } else {
        __nv_bfloat16* orow = (__nv_bfloat16*)outp + (size_t)t * DIMC;
        orow[tid]       = __float2bfloat16(r0);
        orow[tid + 128] = __float2bfloat16(r1);
        orow[tid + 256] = __float2bfloat16(r2);
    }
}

// ---------------- bf16 mma.sync GEMM 128x128 (round-2 proven) ----------------
#define GP 40
template<int MODE, int OUTBF>
__global__ void __launch_bounds__(256) gemm_bf16(
    const __nv_bfloat16* __restrict__ A, const __nv_bfloat16* __restrict__ W,
    const float* __restrict__ bias, const float* __restrict__ res,
    const float* __restrict__ gamma, void* __restrict__ Cout,
    int N, int K)
{
    __shared__ __align__(16) __nv_bfloat16 sA[2][128 * GP];
    __shared__ __align__(16) __nv_bfloat16 sB[2][128 * GP];

    const int tid  = threadIdx.x;
    const int lane = tid & 31;
    const int warp = tid >> 5;
    const int wm = warp >> 1;
    const int wn = warp & 1;
    const size_t bm = (size_t)blockIdx.y * 128;
    const size_t bn = (size_t)blockIdx.x * 128;

    const __nv_bfloat16* Ab = A + bm * (size_t)K;
    const __nv_bfloat16* Wb = W + bn * (size_t)K;

    float c[2][8][4];
    #pragma unroll
    for (int i = 0; i < 2; i++)
        #pragma unroll
        for (int j = 0; j < 8; j++)
            #pragma unroll
            for (int k = 0; k < 4; k++) c[i][j][k] = 0.0f;

    const int lrow = tid >> 2;
    const int loff = (tid & 3) * 8;

    uint4 a0v, a1v, b0v, b1v;
    a0v = *(const uint4*)(Ab + (size_t)lrow * K + loff);
    a1v = *(const uint4*)(Ab + (size_t)(lrow + 64) * K + loff);
    b0v = *(const uint4*)(Wb + (size_t)lrow * K + loff);
    b1v = *(const uint4*)(Wb + (size_t)(lrow + 64) * K + loff);
    *(uint4*)(&sA[0][lrow * GP + loff])        = a0v;
    *(uint4*)(&sA[0][(lrow + 64) * GP + loff]) = a1v;
    *(uint4*)(&sB[0][lrow * GP + loff])        = b0v;
    *(uint4*)(&sB[0][(lrow + 64) * GP + loff]) = b1v;
    __syncthreads();

    const int nk = K >> 5;
    int buf = 0;
    for (int t = 0; t < nk; t++) {
        if (t + 1 < nk) {
            const int kt = (t + 1) << 5;
            a0v = *(const uint4*)(Ab + (size_t)lrow * K + kt + loff);
            a1v = *(const uint4*)(Ab + (size_t)(lrow + 64) * K + kt + loff);
            b0v = *(const uint4*)(Wb + (size_t)lrow * K + kt + loff);
            b1v = *(const uint4*)(Wb + (size_t)(lrow + 64) * K + kt + loff);
        }
        const uint32_t abase = smem_u32(&sA[buf][0]);
        const uint32_t bbase = smem_u32(&sB[buf][0]);
        #pragma unroll
        for (int kk = 0; kk < 2; kk++) {
            uint32_t af[2][4];
            #pragma unroll
            for (int mt = 0; mt < 2; mt++) {
                uint32_t addr = abase +
                    (((wm * 32 + mt * 16 + (lane & 15)) * GP) + kk * 16 + ((lane >> 4) << 3)) * 2;
                ldm_x4(af[mt][0], af[mt][1], af[mt][2], af[mt][3], addr);
            }
            uint32_t bfv[8][2];
            #pragma unroll
            for (int p = 0; p < 4; p++) {
                uint32_t addr = bbase +
                    (((wn * 64 + p * 16 + ((lane >> 4) << 3) + (lane & 7)) * GP) +
                     kk * 16 + (((lane >> 3) & 1) << 3)) * 2;
                ldm_x4(bfv[2 * p][0], bfv[2 * p][1], bfv[2 * p + 1][0], bfv[2 * p + 1][1], addr);
            }
            #pragma unroll
            for (int mt = 0; mt < 2; mt++)
                #pragma unroll
                for (int nt = 0; nt < 8; nt++)
                    mma_bf16(c[mt][nt], af[mt], bfv[nt]);
        }
        if (t + 1 < nk) {
            const int nb = buf ^ 1;
            *(uint4*)(&sA[nb][lrow * GP + loff])        = a0v;
            *(uint4*)(&sA[nb][(lrow + 64) * GP + loff]) = a1v;
            *(uint4*)(&sB[nb][lrow * GP + loff])        = b0v;
            *(uint4*)(&sB[nb][(lrow + 64) * GP + loff]) = b1v;
        }
        __syncthreads();
        buf ^= 1;
    }

    const int r = lane >> 2;
    const int c2 = (lane & 3) * 2;
    #pragma unroll
    for (int mt = 0; mt < 2; mt++) {
        const size_t row0 = bm + wm * 32 + mt * 16 + r;
        const size_t row1 = row0 + 8;
        #pragma unroll
        for (int nt = 0; nt < 8; nt++) {
            const int col = (int)bn + wn * 64 + nt * 8 + c2;
            float b0 = 0.f, b1 = 0.f;
            if (MODE != 0 || bias) { b0 = bias[col]; b1 = bias[col + 1]; }
            float v00 = c[mt][nt][0] + b0, v01 = c[mt][nt][1] + b1;
            float v10 = c[mt][nt][2] + b0, v11 = c[mt][nt][3] + b1;
            if (MODE == 1) {
                v00 = gelu_exact(v00); v01 = gelu_exact(v01);
                v10 = gelu_exact(v10); v11 = gelu_exact(v11);
            } else if (MODE == 2) {
                const float g0 = gamma[col], g1 = gamma[col + 1];
                v00 = res[row0 * N + col] + v00 * g0;
                v01 = res[row0 * N + col + 1] + v01 * g1;
                v10 = res[row1 * N + col] + v10 * g0;
                v11 = res[row1 * N + col + 1] + v11 * g1;
            }
            if (OUTBF) {
                __nv_bfloat16* C = (__nv_bfloat16*)Cout;
                *(__nv_bfloat162*)(C + row0 * N + col) = __floats2bfloat162_rn(v00, v01);
                *(__nv_bfloat162*)(C + row1 * N + col) = __floats2bfloat162_rn(v10, v11);
            } else {
                float* C = (float*)Cout;
                *(float2*)(C + row0 * N + col) = make_float2(v00, v01);
                *(float2*)(C + row1 * N + col) = make_float2(v10, v11);
            }
        }
    }
}

// ---------------- fp8 mma.sync GEMM 128x128 ----------------
template<int MODE, int OUT8>
__global__ void __launch_bounds__(256) gemm_fp8(
    const uint8_t* __restrict__ A, const uint8_t* __restrict__ W,
    const float* __restrict__ bias, void* __restrict__ Cout,
    int N, int K)
{
    __shared__ __align__(16) uint16_t sA[2][128 * GP];
    __shared__ __align__(16) uint16_t sB[2][128 * GP];

    const int tid  = threadIdx.x;
    const int lane = tid & 31;
    const int warp = tid >> 5;
    const int wm = warp >> 1;
    const int wn = warp & 1;
    const size_t bm = (size_t)blockIdx.y * 128;
    const size_t bn = (size_t)blockIdx.x * 128;

    const uint8_t* Ab = A + bm * (size_t)K;
    const uint8_t* Wb = W + bn * (size_t)K;

    float c[2][8][4];
    #pragma unroll
    for (int i = 0; i < 2; i++)
        #pragma unroll
        for (int j = 0; j < 8; j++)
            #pragma unroll
            for (int k = 0; k < 4; k++) c[i][j][k] = 0.0f;

    const int lrow = tid >> 2;
    const int lby  = (tid & 3) * 16;
    const int luo  = (tid & 3) * 8;

    uint4 a0v, a1v, b0v, b1v;
    a0v = *(const uint4*)(Ab + (size_t)lrow * K + lby);
    a1v = *(const uint4*)(Ab + (size_t)(lrow + 64) * K + lby);
    b0v = *(const uint4*)(Wb + (size_t)lrow * K + lby);
    b1v = *(const uint4*)(Wb + (size_t)(lrow + 64) * K + lby);
    *(uint4*)(&sA[0][lrow * GP + luo])        = a0v;
    *(uint4*)(&sA[0][(lrow + 64) * GP + luo]) = a1v;
    *(uint4*)(&sB[0][lrow * GP + luo])        = b0v;
    *(uint4*)(&sB[0][(lrow + 64) * GP + luo]) = b1v;
    __syncthreads();

    const int nk = K >> 6;
    int buf = 0;
    for (int t = 0; t < nk; t++) {
        if (t + 1 < nk) {
            const int kt = (t + 1) << 6;
            a0v = *(const uint4*)(Ab + (size_t)lrow * K + kt + lby);
            a1v = *(const uint4*)(Ab + (size_t)(lrow + 64) * K + kt + lby);
            b0v = *(const uint4*)(Wb + (size_t)lrow * K + kt + lby);
            b1v = *(const uint4*)(Wb + (size_t)(lrow + 64) * K + kt + lby);
        }
        const uint32_t abase = smem_u32(&sA[buf][0]);
        const uint32_t bbase = smem_u32(&sB[buf][0]);
        #pragma unroll
        for (int kk = 0; kk < 2; kk++) {
            uint32_t af[2][4];
            #pragma unroll
            for (int mt = 0; mt < 2; mt++) {
                uint32_t addr = abase +
                    (((wm * 32 + mt * 16 + (lane & 15)) * GP) + kk * 16 + ((lane >> 4) << 3)) * 2;
                ldm_x4(af[mt][0], af[mt][1], af[mt][2], af[mt][3], addr);
            }
            uint32_t bfv[8][2];
            #pragma unroll
            for (int p = 0; p < 4; p++) {
                uint32_t addr = bbase +
                    (((wn * 64 + p * 16 + ((lane >> 4) << 3) + (lane & 7)) * GP) +
                     kk * 16 + (((lane >> 3) & 1) << 3)) * 2;
                ldm_x4(bfv[2 * p][0], bfv[2 * p][1], bfv[2 * p + 1][0], bfv[2 * p + 1][1], addr);
            }
            #pragma unroll
            for (int mt = 0; mt < 2; mt++)
                #pragma unroll
                for (int nt = 0; nt < 8; nt++)
                    mma_fp8(c[mt][nt], af[mt], bfv[nt]);
        }
        if (t + 1 < nk) {
            const int nb = buf ^ 1;
            *(uint4*)(&sA[nb][lrow * GP + luo])        = a0v;
            *(uint4*)(&sA[nb][(lrow + 64) * GP + luo]) = a1v;
            *(uint4*)(&sB[nb][lrow * GP + luo])        = b0v;
            *(uint4*)(&sB[nb][(lrow + 64) * GP + luo]) = b1v;
        }
        __syncthreads();
        buf ^= 1;
    }

    const int r = lane >> 2;
    const int c2 = (lane & 3) * 2;
    #pragma unroll
    for (int mt = 0; mt < 2; mt++) {
        const size_t row0 = bm + wm * 32 + mt * 16 + r;
        const size_t row1 = row0 + 8;
        #pragma unroll
        for (int nt = 0; nt < 8; nt++) {
            const int col = (int)bn + wn * 64 + nt * 8 + c2;
            float b0 = 0.f, b1 = 0.f;
            if (bias) { b0 = bias[col]; b1 = bias[col + 1]; }
            float v00 = c[mt][nt][0] + b0, v01 = c[mt][nt][1] + b1;
            float v10 = c[mt][nt][2] + b0, v11 = c[mt][nt][3] + b1;
            if (MODE == 1) {
                v00 = gelu_exact(v00); v01 = gelu_exact(v01);
                v10 = gelu_exact(v10); v11 = gelu_exact(v11);
            }
            if (OUT8) {
                uint8_t* C = (uint8_t*)Cout;
                *(uint16_t*)(C + row0 * N + col) = packf8(v00, v01);
                *(uint16_t*)(C + row1 * N + col) = packf8(v10, v11);
            } else {
                __nv_bfloat16* C = (__nv_bfloat16*)Cout;
                *(__nv_bfloat162*)(C + row0 * N + col) = __floats2bfloat162_rn(v00, v01);
                *(__nv_bfloat162*)(C + row1 * N + col) = __floats2bfloat162_rn(v10, v11);
            }
        }
    }
}

// ---------------- bf16 flash attention: Q tile 128x64, 256 threads ----------------
#define AQP 72
__global__ void __launch_bounds__(256) attn_bf16(const __nv_bfloat16* __restrict__ qkv,
                                                 __nv_bfloat16* __restrict__ og)
{
    __shared__ __align__(16) __nv_bfloat16 Qs[128 * AQP];
    __shared__ __align__(16) __nv_bfloat16 Ks[64 * AQP];
    __shared__ __align__(16) __nv_bfloat16 Vs[64 * AQP];

    const int b  = blockIdx.z;
    const int h  = blockIdx.y;
    const int qt = blockIdx.x;
    const int tid  = threadIdx.x;
    const int lane = tid & 31;
    const int warp = tid >> 5;
    const size_t base = (size_t)b * SEQ * QKV3;

    // load Q tile: 128 rows x 64 halves = 1024 uint4
    #pragma unroll
    for (int i = 0; i < 4; i++) {
        const int cidx = tid + i * 256;
        const int row = cidx >> 3;
        const int off = (cidx & 7) * 8;
        *(uint4*)(Qs + row * AQP + off) =
            *(const uint4*)(qkv + base + (size_t)(qt * 128 + row) * QKV3 + h * HDIM + off);
    }

    float m_run[2] = { -1e30f, -1e30f };
    float l_run[2] = { 0.0f, 0.0f };
    float o[8][4];
    #pragma unroll
    for (int i = 0; i < 8; i++)
        #pragma unroll
        for (int j = 0; j < 4; j++) o[i][j] = 0.0f;

    const uint32_t qb = smem_u32(Qs);
    const uint32_t kb = smem_u32(Ks);
    const uint32_t vb = smem_u32(Vs);

    for (int kt = 0; kt < 32; kt++) {
        __syncthreads();
        #pragma unroll
        for (int i = 0; i < 2; i++) {
            const int cidx = tid + i * 256;
            const int row = cidx >> 3;
            const int off = (cidx & 7) * 8;
            const size_t g = base + (size_t)(kt * 64 + row) * QKV3 + h * HDIM + off;
            *(uint4*)(Ks + row * AQP + off) = *(const uint4*)(qkv + g + DIMC);
            *(uint4*)(Vs + row * AQP + off) = *(const uint4*)(qkv + g + 2 * DIMC);
        }
        __syncthreads();

        float s[8][4];
        #pragma unroll
        for (int i = 0; i < 8; i++)
            #pragma unroll
            for (int j = 0; j < 4; j++) s[i][j] = 0.0f;

        #pragma unroll
        for (int ks = 0; ks < 4; ks++) {
            uint32_t a[4];
            uint32_t aaddr = qb + (((warp * 16 + (lane & 15)) * AQP) + ks * 16 + ((lane >> 4) << 3)) * 2;
            ldm_x4(a[0], a[1], a[2], a[3], aaddr);
            uint32_t bbv[8][2];
            #pragma unroll
            for (int p = 0; p < 4; p++) {
                uint32_t baddr = kb + (((p * 16 + ((lane >> 4) << 3) + (lane & 7)) * AQP) +
                                       ks * 16 + (((lane >> 3) & 1) << 3)) * 2;
                ldm_x4(bbv[2 * p][0], bbv[2 * p][1], bbv[2 * p + 1][0], bbv[2 * p + 1][1], baddr);
            }
            #pragma unroll
            for (int nt = 0; nt < 8; nt++) mma_bf16(s[nt], a, bbv[nt]);
        }

        #pragma unroll
        for (int rr = 0; rr < 2; rr++) {
            float rmax = s[0][rr * 2];
            #pragma unroll
            for (int nt = 0; nt < 8; nt++) {
                rmax = fmaxf(rmax, s[nt][rr * 2]);
                rmax = fmaxf(rmax, s[nt][rr * 2 + 1]);
            }
            rmax = fmaxf(rmax, __shfl_xor_sync(0xffffffffu, rmax, 1));
            rmax = fmaxf(rmax, __shfl_xor_sync(0xffffffffu, rmax, 2));
            const float mn = fmaxf(m_run[rr], rmax * 0.125f);
            const float corr = __expf(m_run[rr] - mn);
            m_run[rr] = mn;
            float rs = 0.0f;
            #pragma unroll
            for (int nt = 0; nt < 8; nt++) {
                float p0 = __expf(s[nt][rr * 2] * 0.125f - mn);
                float p1 = __expf(s[nt][rr * 2 + 1] * 0.125f - mn);
                s[nt][rr * 2] = p0; s[nt][rr * 2 + 1] = p1;
                rs += p0 + p1;
            }
            rs += __shfl_xor_sync(0xffffffffu, rs, 1);
            rs += __shfl_xor_sync(0xffffffffu, rs, 2);
            l_run[rr] = l_run[rr] * corr + rs;
            #pragma unroll
            for (int dt = 0; dt < 8; dt++) {
                o[dt][rr * 2] *= corr;
                o[dt][rr * 2 + 1] *= corr;
            }
        }

        #pragma unroll
        for (int j = 0; j < 4; j++) {
            uint32_t aP[4];
            aP[0] = packbf(s[2 * j][0], s[2 * j][1]);
            aP[1] = packbf(s[2 * j][2], s[2 * j][3]);
            aP[2] = packbf(s[2 * j + 1][0], s[2 * j + 1][1]);
            aP[3] = packbf(s[2 * j + 1][2], s[2 * j + 1][3]);
            uint32_t bv[8][2];
            #pragma unroll
            for (int p = 0; p < 4; p++) {
                uint32_t baddr = vb + (((j * 16 + (lane & 7) + (((lane >> 3) & 1) << 3)) * AQP) +
                                       p * 16 + ((lane >> 4) << 3)) * 2;
                ldm_x4_t(bv[2 * p][0], bv[2 * p][1], bv[2 * p + 1][0], bv[2 * p + 1][1], baddr);
            }
            #pragma unroll
            for (int dt = 0; dt < 8; dt++) mma_bf16(o[dt], aP, bv[dt]);
        }
    }

    const float linv0 = 1.0f / l_run[0];
    const float linv1 = 1.0f / l_run[1];
    const int row0 = qt * 128 + warp * 16 + (lane >> 2);
    __nv_bfloat16* out0 = og + ((size_t)(b * SEQ) + row0) * DIMC + h * HDIM + (lane & 3) * 2;
    #pragma unroll
    for (int dt = 0; dt < 8; dt++) {
        *(__nv_bfloat162*)(out0 + dt * 8) =
            __floats2bfloat162_rn(o[dt][0] * linv0, o[dt][1] * linv0);
        *(__nv_bfloat162*)(out0 + 8 * DIMC + dt * 8) =
            __floats2bfloat162_rn(o[dt][2] * linv1, o[dt][3] * linv1);
    }
}

// ---------------- launch ----------------
extern "C" void kernel_launch(void* const* d_in, const int* in_sizes, int n_in,
                              void* d_out, int out_size)
{
    const float* x      = (const float*)d_in[0];
    const float* qkv_w  = (const float*)d_in[1];
    const float* qkv_b  = (const float*)d_in[2];
    const float* proj_w = (const float*)d_in[3];
    const float* proj_b = (const float*)d_in[4];
    const float* fc1_w  = (const float*)d_in[5];
    const float* fc1_b  = (const float*)d_in[6];
    const float* eye1_w = (const float*)d_in[7];
    const float* eye2_w = (const float*)d_in[8];
    const float* fc2_w  = (const float*)d_in[9];
    const float* fc2_b  = (const float*)d_in[10];
    const float* n1w    = (const float*)d_in[11];
    const float* n1b    = (const float*)d_in[12];
    const float* n2w    = (const float*)d_in[13];
    const float* n2b    = (const float*)d_in[14];
    const float* ls1    = (const float*)d_in[15];
    const float* ls2    = (const float*)d_in[16];
    float* out = (float*)d_out;

    __nv_bfloat16 *hb, *qkvb, *ob, *ab, *wqkv, *wproj, *wfc2;
    uint8_t *h8, *a8, *b8, *wfc1_8, *weye1_8, *weye2_8;
    cudaGetSymbolAddress((void**)&hb,   g_hb);
    cudaGetSymbolAddress((void**)&h8,   g_h8);
    cudaGetSymbolAddress((void**)&qkvb, g_qkvb);
    cudaGetSymbolAddress((void**)&ob,   g_ob);
    cudaGetSymbolAddress((void**)&a8,   g_a8);
    cudaGetSymbolAddress((void**)&b8,   g_b8);
    cudaGetSymbolAddress((void**)&ab,   g_ab);
    cudaGetSymbolAddress((void**)&wqkv,    g_wqkv);
    cudaGetSymbolAddress((void**)&wproj,   g_wproj);
    cudaGetSymbolAddress((void**)&wfc2,    g_wfc2);
    cudaGetSymbolAddress((void**)&wfc1_8,  g_wfc1_8);
    cudaGetSymbolAddress((void**)&weye1_8, g_weye1_8);
    cudaGetSymbolAddress((void**)&weye2_8, g_weye2_8);

    const int CT = 256;

    // launches 0-2: bf16 weight converts
    f2bf_kernel<<<(QKV3 * DIMC / 4 + CT - 1) / CT, CT>>>(qkv_w,  wqkv,  QKV3 * DIMC);   // 0
    f2bf_kernel<<<(DIMC * DIMC / 4 + CT - 1) / CT, CT>>>(proj_w, wproj, DIMC * DIMC);   // 1
    f2bf_kernel<<<(DIMC * HID / 4 + CT - 1) / CT, CT>>>(fc2_w,  wfc2,  DIMC * HID);     // 2

    const dim3 blk(256);

    // 3: h = LN1(x) -> bf16
    ln_kernel<0><<<NTOK, 128>>>(x, n1w, n1b, hb);
    // 4: qkv = h @ qkv_w^T + qkv_b -> bf16
    gemm_bf16<0, 1><<<dim3(QKV3 / 128, NTOK / 128), blk>>>(hb, wqkv, qkv_b, nullptr, nullptr, qkvb, QKV3, DIMC);
    // 5: o = attention(qkv)   <-- ncu -s 5 -c 1 captures THIS
    attn_bf16<<<dim3(SEQ / 128, HEADS, BATCH), 256>>>(qkvb, ob);
    // 6: out = x + (o @ proj_w^T + proj_b) * ls1 -> fp32
    gemm_bf16<2, 0><<<dim3(DIMC / 128, NTOK / 128), blk>>>(ob, wproj, proj_b, x, ls1, out, DIMC, DIMC);

    // fp8 weight converts (needed from step 9 on)
    f2f8_kernel<<<(HID * DIMC / 4 + CT - 1) / CT, CT>>>(fc1_w,  wfc1_8,  HID * DIMC);
    f2f8_kernel<<<(HID * HID / 4 + CT - 1) / CT, CT>>>(eye1_w, weye1_8, HID * HID);
    f2f8_kernel<<<(HID * HID / 4 + CT - 1) / CT, CT>>>(eye2_w, weye2_8, HID * HID);

    // 8: h8 = LN2(out) -> fp8
    ln_kernel<1><<<NTOK, 128>>>(out, n2w, n2b, h8);
    // 9: a8 = gelu(h8 @ fc1_w^T + fc1_b) -> fp8
    gemm_fp8<1, 1><<<dim3(HID / 128, NTOK / 128), blk>>>(h8, wfc1_8, fc1_b, a8, HID, DIMC);
    // 10: b8 = a8 @ eye1_w^T -> fp8
    gemm_fp8<0, 1><<<dim3(HID / 128, NTOK / 128), blk>>>(a8, weye1_8, nullptr, b8, HID, HID);
    // 11: ab = b8 @ eye2_w^T -> bf16
    gemm_fp8<0, 0><<<dim3(HID / 128, NTOK / 128), blk>>>(b8, weye2_8, nullptr, ab, HID, HID);
    // 12: out = out + (ab @ fc2_w^T + fc2_b) * ls2 -> fp32
    gemm_bf16<2, 0><<<dim3(DIMC / 128, NTOK / 128), blk>>>(ab, wfc2, fc2_b, out, ls2, out, DIMC, HID);
}

// round 8
// speedup vs baseline: 1.0015x; 1.0015x over previous
#include <cuda_runtime.h>
#include <cuda_bf16.h>
#include <cuda_fp8.h>
#include <math.h>
#include <stdint.h>

// ---------------- problem constants ----------------
#define NTOK 16384      // 8 * 2048 tokens
#define SEQ  2048
#define BATCH 8
#define DIMC 384
#define QKV3 1152
#define HID  1536
#define HEADS 6
#define HDIM 64
#define EPSV 1e-5f

// ---------------- scratch (device globals) ----------------
__device__ __nv_bfloat16 g_hb  [(size_t)NTOK * DIMC];   // LN1 out (bf16)
__device__ uint8_t       g_h8  [(size_t)NTOK * DIMC];   // LN2 out (fp8)
__device__ __nv_bfloat16 g_qkvb[(size_t)NTOK * QKV3];
__device__ __nv_bfloat16 g_ob  [(size_t)NTOK * DIMC];
__device__ uint8_t       g_a8  [(size_t)NTOK * HID];    // fc1 out (fp8)
__device__ uint8_t       g_b8  [(size_t)NTOK * HID];    // eye1 out (fp8)
__device__ __nv_bfloat16 g_ab  [(size_t)NTOK * HID];    // eye2 out (bf16)
__device__ __nv_bfloat16 g_wqkv [(size_t)QKV3 * DIMC];
__device__ __nv_bfloat16 g_wproj[(size_t)DIMC * DIMC];
__device__ __nv_bfloat16 g_wfc2 [(size_t)DIMC * HID];
__device__ uint8_t       g_wfc1_8 [(size_t)HID * DIMC];
__device__ uint8_t       g_weye1_8[(size_t)HID * HID];
__device__ uint8_t       g_weye2_8[(size_t)HID * HID];

// ---------------- helpers ----------------
__device__ __forceinline__ uint32_t smem_u32(const void* p) {
    return (uint32_t)__cvta_generic_to_shared(p);
}
__device__ __forceinline__ void cp16u(uint32_t dst, const void* src) {
    asm volatile("cp.async.cg.shared.global [%0],[%1],16;\n" :: "r"(dst), "l"(src));
}
__device__ __forceinline__ void cp_commit() { asm volatile("cp.async.commit_group;\n"); }
template<int N>
__device__ __forceinline__ void cp_wait() { asm volatile("cp.async.wait_group %0;\n" :: "n"(N)); }
__device__ __forceinline__ void ldm_x4(uint32_t& r0, uint32_t& r1, uint32_t& r2, uint32_t& r3, uint32_t a) {
    asm volatile("ldmatrix.sync.aligned.m8n8.x4.shared.b16 {%0,%1,%2,%3},[%4];\n"
                 : "=r"(r0), "=r"(r1), "=r"(r2), "=r"(r3) : "r"(a));
}
__device__ __forceinline__ void ldm_x4_t(uint32_t& r0, uint32_t& r1, uint32_t& r2, uint32_t& r3, uint32_t a) {
    asm volatile("ldmatrix.sync.aligned.m8n8.x4.trans.shared.b16 {%0,%1,%2,%3},[%4];\n"
                 : "=r"(r0), "=r"(r1), "=r"(r2), "=r"(r3) : "r"(a));
}
__device__ __forceinline__ void mma_bf16(float c[4], const uint32_t a[4], const uint32_t b[2]) {
    asm volatile(
        "mma.sync.aligned.m16n8k16.row.col.f32.bf16.bf16.f32 "
        "{%0,%1,%2,%3},{%4,%5,%6,%7},{%8,%9},{%0,%1,%2,%3};\n"
        : "+f"(c[0]), "+f"(c[1]), "+f"(c[2]), "+f"(c[3])
        : "r"(a[0]), "r"(a[1]), "r"(a[2]), "r"(a[3]), "r"(b[0]), "r"(b[1]));
}
__device__ __forceinline__ void mma_fp8(float c[4], const uint32_t a[4], const uint32_t b[2]) {
    asm volatile(
        "mma.sync.aligned.m16n8k32.row.col.f32.e4m3.e4m3.f32 "
        "{%0,%1,%2,%3},{%4,%5,%6,%7},{%8,%9},{%0,%1,%2,%3};\n"
        : "+f"(c[0]), "+f"(c[1]), "+f"(c[2]), "+f"(c[3])
        : "r"(a[0]), "r"(a[1]), "r"(a[2]), "r"(a[3]), "r"(b[0]), "r"(b[1]));
}
__device__ __forceinline__ uint32_t packbf(float lo, float hi) {
    __nv_bfloat162 h = __floats2bfloat162_rn(lo, hi);
    return *reinterpret_cast<uint32_t*>(&h);
}
__device__ __forceinline__ uint16_t packf8(float lo, float hi) {
    return (uint16_t)__nv_cvt_float2_to_fp8x2(make_float2(lo, hi), __NV_SATFINITE, __NV_E4M3);
}
__device__ __forceinline__ float gelu_exact(float x) {
    return 0.5f * x * (1.0f + erff(x * 0.7071067811865475f));
}

// ---------------- weight converts ----------------
__global__ void f2bf_kernel(const float* __restrict__ in, __nv_bfloat16* __restrict__ out, int n) {
    int i = (blockIdx.x * blockDim.x + threadIdx.x) * 4;
    if (i < n) {
        float4 v = *(const float4*)(in + i);
        *(__nv_bfloat162*)(out + i)     = __floats2bfloat162_rn(v.x, v.y);
        *(__nv_bfloat162*)(out + i + 2) = __floats2bfloat162_rn(v.z, v.w);
    }
}
__global__ void f2f8_kernel(const float* __restrict__ in, uint8_t* __restrict__ out, int n) {
    int i = (blockIdx.x * blockDim.x + threadIdx.x) * 4;
    if (i < n) {
        float4 v = *(const float4*)(in + i);
        uint32_t lo = packf8(v.x, v.y);
        uint32_t hi = packf8(v.z, v.w);
        *(uint32_t*)(out + i) = lo | (hi << 16);
    }
}

// ---------------- LayerNorm ----------------
template<int OUT8>
__global__ void ln_kernel(const float* __restrict__ x, const float* __restrict__ w,
                          const float* __restrict__ b, void* __restrict__ outp)
{
    const int t = blockIdx.x;
    const float* xr = x + (size_t)t * DIMC;
    const int tid = threadIdx.x;

    float v0 = xr[tid], v1 = xr[tid + 128], v2 = xr[tid + 256];
    float s = v0 + v1 + v2;
    float q = v0 * v0 + v1 * v1 + v2 * v2;
    #pragma unroll
    for (int off = 16; off > 0; off >>= 1) {
        s += __shfl_xor_sync(0xffffffffu, s, off);
        q += __shfl_xor_sync(0xffffffffu, q, off);
    }
    __shared__ float ss[4], qq[4];
    if ((tid & 31) == 0) { ss[tid >> 5] = s; qq[tid >> 5] = q; }
    __syncthreads();
    s = ss[0] + ss[1] + ss[2] + ss[3];
    q = qq[0] + qq[1] + qq[2] + qq[3];
    const float mean = s * (1.0f / DIMC);
    const float var  = q * (1.0f / DIMC) - mean * mean;
    const float inv  = rsqrtf(var + EPSV);

    const float r0 = (v0 - mean) * inv * w[tid]       + b[tid];
    const float r1 = (v1 - mean) * inv * w[tid + 128] + b[tid + 128];
    const float r2 = (v2 - mean) * inv * w[tid + 256] + b[tid + 256];
    if (OUT8) {
        uint8_t* orow = (uint8_t*)outp + (size_t)t * DIMC;
        orow[tid]       = (uint8_t)__nv_cvt_float_to_fp8(r0, __NV_SATFINITE, __NV_E4M3);
        orow[tid + 128] = (uint8_t)__nv_cvt_float_to_fp8(r1, __NV_SATFINITE, __NV_E4M3);
        orow[tid + 256] = (uint8_t)__nv_cvt_float_to_fp8(r2, __NV_SATFINITE, __NV_E4M3);
    } else {
        __nv_bfloat16* orow = (__nv_bfloat16*)outp + (size_t)t * DIMC;
        orow[tid]       = __float2bfloat16(r0);
        orow[tid + 128] = __float2bfloat16(r1);
        orow[tid + 256] = __float2bfloat16(r2);
    }
}

// ---------------- bf16 mma.sync GEMM 128x128 (round-2 proven) ----------------
#define GP 40
template<int MODE, int OUTBF>
__global__ void __launch_bounds__(256) gemm_bf16(
    const __nv_bfloat16* __restrict__ A, const __nv_bfloat16* __restrict__ W,
    const float* __restrict__ bias, const float* __restrict__ res,
    const float* __restrict__ gamma, void* __restrict__ Cout,
    int N, int K)
{
    __shared__ __align__(16) __nv_bfloat16 sA[2][128 * GP];
    __shared__ __align__(16) __nv_bfloat16 sB[2][128 * GP];

    const int tid  = threadIdx.x;
    const int lane = tid & 31;
    const int warp = tid >> 5;
    const int wm = warp >> 1;
    const int wn = warp & 1;
    const size_t bm = (size_t)blockIdx.y * 128;
    const size_t bn = (size_t)blockIdx.x * 128;

    const __nv_bfloat16* Ab = A + bm * (size_t)K;
    const __nv_bfloat16* Wb = W + bn * (size_t)K;

    float c[2][8][4];
    #pragma unroll
    for (int i = 0; i < 2; i++)
        #pragma unroll
        for (int j = 0; j < 8; j++)
            #pragma unroll
            for (int k = 0; k < 4; k++) c[i][j][k] = 0.0f;

    const int lrow = tid >> 2;
    const int loff = (tid & 3) * 8;

    uint4 a0v, a1v, b0v, b1v;
    a0v = *(const uint4*)(Ab + (size_t)lrow * K + loff);
    a1v = *(const uint4*)(Ab + (size_t)(lrow + 64) * K + loff);
    b0v = *(const uint4*)(Wb + (size_t)lrow * K + loff);
    b1v = *(const uint4*)(Wb + (size_t)(lrow + 64) * K + loff);
    *(uint4*)(&sA[0][lrow * GP + loff])        = a0v;
    *(uint4*)(&sA[0][(lrow + 64) * GP + loff]) = a1v;
    *(uint4*)(&sB[0][lrow * GP + loff])        = b0v;
    *(uint4*)(&sB[0][(lrow + 64) * GP + loff]) = b1v;
    __syncthreads();

    const int nk = K >> 5;
    int buf = 0;
    for (int t = 0; t < nk; t++) {
        if (t + 1 < nk) {
            const int kt = (t + 1) << 5;
            a0v = *(const uint4*)(Ab + (size_t)lrow * K + kt + loff);
            a1v = *(const uint4*)(Ab + (size_t)(lrow + 64) * K + kt + loff);
            b0v = *(const uint4*)(Wb + (size_t)lrow * K + kt + loff);
            b1v = *(const uint4*)(Wb + (size_t)(lrow + 64) * K + kt + loff);
        }
        const uint32_t abase = smem_u32(&sA[buf][0]);
        const uint32_t bbase = smem_u32(&sB[buf][0]);
        #pragma unroll
        for (int kk = 0; kk < 2; kk++) {
            uint32_t af[2][4];
            #pragma unroll
            for (int mt = 0; mt < 2; mt++) {
                uint32_t addr = abase +
                    (((wm * 32 + mt * 16 + (lane & 15)) * GP) + kk * 16 + ((lane >> 4) << 3)) * 2;
                ldm_x4(af[mt][0], af[mt][1], af[mt][2], af[mt][3], addr);
            }
            uint32_t bfv[8][2];
            #pragma unroll
            for (int p = 0; p < 4; p++) {
                uint32_t addr = bbase +
                    (((wn * 64 + p * 16 + ((lane >> 4) << 3) + (lane & 7)) * GP) +
                     kk * 16 + (((lane >> 3) & 1) << 3)) * 2;
                ldm_x4(bfv[2 * p][0], bfv[2 * p][1], bfv[2 * p + 1][0], bfv[2 * p + 1][1], addr);
            }
            #pragma unroll
            for (int mt = 0; mt < 2; mt++)
                #pragma unroll
                for (int nt = 0; nt < 8; nt++)
                    mma_bf16(c[mt][nt], af[mt], bfv[nt]);
        }
        if (t + 1 < nk) {
            const int nb = buf ^ 1;
            *(uint4*)(&sA[nb][lrow * GP + loff])        = a0v;
            *(uint4*)(&sA[nb][(lrow + 64) * GP + loff]) = a1v;
            *(uint4*)(&sB[nb][lrow * GP + loff])        = b0v;
            *(uint4*)(&sB[nb][(lrow + 64) * GP + loff]) = b1v;
        }
        __syncthreads();
        buf ^= 1;
    }

    const int r = lane >> 2;
    const int c2 = (lane & 3) * 2;
    #pragma unroll
    for (int mt = 0; mt < 2; mt++) {
        const size_t row0 = bm + wm * 32 + mt * 16 + r;
        const size_t row1 = row0 + 8;
        #pragma unroll
        for (int nt = 0; nt < 8; nt++) {
            const int col = (int)bn + wn * 64 + nt * 8 + c2;
            float b0 = 0.f, b1 = 0.f;
            if (MODE != 0 || bias) { b0 = bias[col]; b1 = bias[col + 1]; }
            float v00 = c[mt][nt][0] + b0, v01 = c[mt][nt][1] + b1;
            float v10 = c[mt][nt][2] + b0, v11 = c[mt][nt][3] + b1;
            if (MODE == 1) {
                v00 = gelu_exact(v00); v01 = gelu_exact(v01);
                v10 = gelu_exact(v10); v11 = gelu_exact(v11);
            } else if (MODE == 2) {
                const float g0 = gamma[col], g1 = gamma[col + 1];
                v00 = res[row0 * N + col] + v00 * g0;
                v01 = res[row0 * N + col + 1] + v01 * g1;
                v10 = res[row1 * N + col] + v10 * g0;
                v11 = res[row1 * N + col + 1] + v11 * g1;
            }
            if (OUTBF) {
                __nv_bfloat16* C = (__nv_bfloat16*)Cout;
                *(__nv_bfloat162*)(C + row0 * N + col) = __floats2bfloat162_rn(v00, v01);
                *(__nv_bfloat162*)(C + row1 * N + col) = __floats2bfloat162_rn(v10, v11);
            } else {
                float* C = (float*)Cout;
                *(float2*)(C + row0 * N + col) = make_float2(v00, v01);
                *(float2*)(C + row1 * N + col) = make_float2(v10, v11);
            }
        }
    }
}

// ---------------- fp8 mma.sync GEMM 128x128 ----------------
template<int MODE, int OUT8>
__global__ void __launch_bounds__(256) gemm_fp8(
    const uint8_t* __restrict__ A, const uint8_t* __restrict__ W,
    const float* __restrict__ bias, void* __restrict__ Cout,
    int N, int K)
{
    __shared__ __align__(16) uint16_t sA[2][128 * GP];
    __shared__ __align__(16) uint16_t sB[2][128 * GP];

    const int tid  = threadIdx.x;
    const int lane = tid & 31;
    const int warp = tid >> 5;
    const int wm = warp >> 1;
    const int wn = warp & 1;
    const size_t bm = (size_t)blockIdx.y * 128;
    const size_t bn = (size_t)blockIdx.x * 128;

    const uint8_t* Ab = A + bm * (size_t)K;
    const uint8_t* Wb = W + bn * (size_t)K;

    float c[2][8][4];
    #pragma unroll
    for (int i = 0; i < 2; i++)
        #pragma unroll
        for (int j = 0; j < 8; j++)
            #pragma unroll
            for (int k = 0; k < 4; k++) c[i][j][k] = 0.0f;

    const int lrow = tid >> 2;
    const int lby  = (tid & 3) * 16;
    const int luo  = (tid & 3) * 8;

    uint4 a0v, a1v, b0v, b1v;
    a0v = *(const uint4*)(Ab + (size_t)lrow * K + lby);
    a1v = *(const uint4*)(Ab + (size_t)(lrow + 64) * K + lby);
    b0v = *(const uint4*)(Wb + (size_t)lrow * K + lby);
    b1v = *(const uint4*)(Wb + (size_t)(lrow + 64) * K + lby);
    *(uint4*)(&sA[0][lrow * GP + luo])        = a0v;
    *(uint4*)(&sA[0][(lrow + 64) * GP + luo]) = a1v;
    *(uint4*)(&sB[0][lrow * GP + luo])        = b0v;
    *(uint4*)(&sB[0][(lrow + 64) * GP + luo]) = b1v;
    __syncthreads();

    const int nk = K >> 6;
    int buf = 0;
    for (int t = 0; t < nk; t++) {
        if (t + 1 < nk) {
            const int kt = (t + 1) << 6;
            a0v = *(const uint4*)(Ab + (size_t)lrow * K + kt + lby);
            a1v = *(const uint4*)(Ab + (size_t)(lrow + 64) * K + kt + lby);
            b0v = *(const uint4*)(Wb + (size_t)lrow * K + kt + lby);
            b1v = *(const uint4*)(Wb + (size_t)(lrow + 64) * K + kt + lby);
        }
        const uint32_t abase = smem_u32(&sA[buf][0]);
        const uint32_t bbase = smem_u32(&sB[buf][0]);
        #pragma unroll
        for (int kk = 0; kk < 2; kk++) {
            uint32_t af[2][4];
            #pragma unroll
            for (int mt = 0; mt < 2; mt++) {
                uint32_t addr = abase +
                    (((wm * 32 + mt * 16 + (lane & 15)) * GP) + kk * 16 + ((lane >> 4) << 3)) * 2;
                ldm_x4(af[mt][0], af[mt][1], af[mt][2], af[mt][3], addr);
            }
            uint32_t bfv[8][2];
            #pragma unroll
            for (int p = 0; p < 4; p++) {
                uint32_t addr = bbase +
                    (((wn * 64 + p * 16 + ((lane >> 4) << 3) + (lane & 7)) * GP) +
                     kk * 16 + (((lane >> 3) & 1) << 3)) * 2;
                ldm_x4(bfv[2 * p][0], bfv[2 * p][1], bfv[2 * p + 1][0], bfv[2 * p + 1][1], addr);
            }
            #pragma unroll
            for (int mt = 0; mt < 2; mt++)
                #pragma unroll
                for (int nt = 0; nt < 8; nt++)
                    mma_fp8(c[mt][nt], af[mt], bfv[nt]);
        }
        if (t + 1 < nk) {
            const int nb = buf ^ 1;
            *(uint4*)(&sA[nb][lrow * GP + luo])        = a0v;
            *(uint4*)(&sA[nb][(lrow + 64) * GP + luo]) = a1v;
            *(uint4*)(&sB[nb][lrow * GP + luo])        = b0v;
            *(uint4*)(&sB[nb][(lrow + 64) * GP + luo]) = b1v;
        }
        __syncthreads();
        buf ^= 1;
    }

    const int r = lane >> 2;
    const int c2 = (lane & 3) * 2;
    #pragma unroll
    for (int mt = 0; mt < 2; mt++) {
        const size_t row0 = bm + wm * 32 + mt * 16 + r;
        const size_t row1 = row0 + 8;
        #pragma unroll
        for (int nt = 0; nt < 8; nt++) {
            const int col = (int)bn + wn * 64 + nt * 8 + c2;
            float b0 = 0.f, b1 = 0.f;
            if (bias) { b0 = bias[col]; b1 = bias[col + 1]; }
            float v00 = c[mt][nt][0] + b0, v01 = c[mt][nt][1] + b1;
            float v10 = c[mt][nt][2] + b0, v11 = c[mt][nt][3] + b1;
            if (MODE == 1) {
                v00 = gelu_exact(v00); v01 = gelu_exact(v01);
                v10 = gelu_exact(v10); v11 = gelu_exact(v11);
            }
            if (OUT8) {
                uint8_t* C = (uint8_t*)Cout;
                *(uint16_t*)(C + row0 * N + col) = packf8(v00, v01);
                *(uint16_t*)(C + row1 * N + col) = packf8(v10, v11);
            } else {
                __nv_bfloat16* C = (__nv_bfloat16*)Cout;
                *(__nv_bfloat162*)(C + row0 * N + col) = __floats2bfloat162_rn(v00, v01);
                *(__nv_bfloat162*)(C + row1 * N + col) = __floats2bfloat162_rn(v10, v11);
            }
        }
    }
}

// ---------------- bf16 flash attention: Q 128x64, 256 threads, cp.async KV pipeline ----------------
#define AQP 72
#define ATTN_SMEM ((128 * AQP + 4 * 64 * AQP) * (int)sizeof(__nv_bfloat16))
__global__ void __launch_bounds__(256) attn_bf16(const __nv_bfloat16* __restrict__ qkv,
                                                 __nv_bfloat16* __restrict__ og)
{
    extern __shared__ __align__(16) __nv_bfloat16 asm_[];
    __nv_bfloat16* Qs = asm_;                       // [128][AQP]
    __nv_bfloat16* Ks = Qs + 128 * AQP;             // [2][64][AQP]
    __nv_bfloat16* Vs = Ks + 2 * 64 * AQP;          // [2][64][AQP]

    const int b  = blockIdx.z;
    const int h  = blockIdx.y;
    const int qt = blockIdx.x;
    const int tid  = threadIdx.x;
    const int lane = tid & 31;
    const int warp = tid >> 5;
    const size_t base = (size_t)b * SEQ * QKV3;

    // load Q tile: 128 rows x 64 halves = 1024 uint4
    #pragma unroll
    for (int i = 0; i < 4; i++) {
        const int cidx = tid + i * 256;
        const int row = cidx >> 3;
        const int off = (cidx & 7) * 8;
        *(uint4*)(Qs + row * AQP + off) =
            *(const uint4*)(qkv + base + (size_t)(qt * 128 + row) * QKV3 + h * HDIM + off);
    }

    // KV tile loader via cp.async (stage s)
    auto load_kv = [&](int kt, int s) {
        __nv_bfloat16* Kd = Ks + s * 64 * AQP;
        __nv_bfloat16* Vd = Vs + s * 64 * AQP;
        #pragma unroll
        for (int i = 0; i < 2; i++) {
            const int cidx = tid + i * 256;
            const int row = cidx >> 3;
            const int off = (cidx & 7) * 8;
            const __nv_bfloat16* g = qkv + base + (size_t)(kt * 64 + row) * QKV3 + h * HDIM + off;
            cp16u(smem_u32(Kd + row * AQP + off), g + DIMC);
            cp16u(smem_u32(Vd + row * AQP + off), g + 2 * DIMC);
        }
    };

    float m_run[2] = { -1e30f, -1e30f };
    float l_run[2] = { 0.0f, 0.0f };
    float o[8][4];
    #pragma unroll
    for (int i = 0; i < 8; i++)
        #pragma unroll
        for (int j = 0; j < 4; j++) o[i][j] = 0.0f;

    const uint32_t qb = smem_u32(Qs);

    load_kv(0, 0);
    cp_commit();

    int buf = 0;
    for (int kt = 0; kt < 32; kt++) {
        if (kt + 1 < 32) load_kv(kt + 1, buf ^ 1);
        cp_commit();
        cp_wait<1>();
        __syncthreads();

        const uint32_t kb = smem_u32(Ks + buf * 64 * AQP);
        const uint32_t vb = smem_u32(Vs + buf * 64 * AQP);

        float s[8][4];
        #pragma unroll
        for (int i = 0; i < 8; i++)
            #pragma unroll
            for (int j = 0; j < 4; j++) s[i][j] = 0.0f;

        #pragma unroll
        for (int ks = 0; ks < 4; ks++) {
            uint32_t a[4];
            uint32_t aaddr = qb + (((warp * 16 + (lane & 15)) * AQP) + ks * 16 + ((lane >> 4) << 3)) * 2;
            ldm_x4(a[0], a[1], a[2], a[3], aaddr);
            uint32_t bbv[8][2];
            #pragma unroll
            for (int p = 0; p < 4; p++) {
                uint32_t baddr = kb + (((p * 16 + ((lane >> 4) << 3) + (lane & 7)) * AQP) +
                                       ks * 16 + (((lane >> 3) & 1) << 3)) * 2;
                ldm_x4(bbv[2 * p][0], bbv[2 * p][1], bbv[2 * p + 1][0], bbv[2 * p + 1][1], baddr);
            }
            #pragma unroll
            for (int nt = 0; nt < 8; nt++) mma_bf16(s[nt], a, bbv[nt]);
        }

        #pragma unroll
        for (int rr = 0; rr < 2; rr++) {
            float rmax = s[0][rr * 2];
            #pragma unroll
            for (int nt = 0; nt < 8; nt++) {
                rmax = fmaxf(rmax, s[nt][rr * 2]);
                rmax = fmaxf(rmax, s[nt][rr * 2 + 1]);
            }
            rmax = fmaxf(rmax, __shfl_xor_sync(0xffffffffu, rmax, 1));
            rmax = fmaxf(rmax, __shfl_xor_sync(0xffffffffu, rmax, 2));
            const float mn = fmaxf(m_run[rr], rmax * 0.125f);
            const float corr = __expf(m_run[rr] - mn);
            m_run[rr] = mn;
            float rs = 0.0f;
            #pragma unroll
            for (int nt = 0; nt < 8; nt++) {
                float p0 = __expf(s[nt][rr * 2] * 0.125f - mn);
                float p1 = __expf(s[nt][rr * 2 + 1] * 0.125f - mn);
                s[nt][rr * 2] = p0; s[nt][rr * 2 + 1] = p1;
                rs += p0 + p1;
            }
            rs += __shfl_xor_sync(0xffffffffu, rs, 1);
            rs += __shfl_xor_sync(0xffffffffu, rs, 2);
            l_run[rr] = l_run[rr] * corr + rs;
            #pragma unroll
            for (int dt = 0; dt < 8; dt++) {
                o[dt][rr * 2] *= corr;
                o[dt][rr * 2 + 1] *= corr;
            }
        }

        #pragma unroll
        for (int j = 0; j < 4; j++) {
            uint32_t aP[4];
            aP[0] = packbf(s[2 * j][0], s[2 * j][1]);
            aP[1] = packbf(s[2 * j][2], s[2 * j][3]);
            aP[2] = packbf(s[2 * j + 1][0], s[2 * j + 1][1]);
            aP[3] = packbf(s[2 * j + 1][2], s[2 * j + 1][3]);
            uint32_t bv[8][2];
            #pragma unroll
            for (int p = 0; p < 4; p++) {
                uint32_t baddr = vb + (((j * 16 + (lane & 7) + (((lane >> 3) & 1) << 3)) * AQP) +
                                       p * 16 + ((lane >> 4) << 3)) * 2;
                ldm_x4_t(bv[2 * p][0], bv[2 * p][1], bv[2 * p + 1][0], bv[2 * p + 1][1], baddr);
            }
            #pragma unroll
            for (int dt = 0; dt < 8; dt++) mma_bf16(o[dt], aP, bv[dt]);
        }
        __syncthreads();
        buf ^= 1;
    }

    const float linv0 = 1.0f / l_run[0];
    const float linv1 = 1.0f / l_run[1];
    const int row0 = qt * 128 + warp * 16 + (lane >> 2);
    __nv_bfloat16* out0 = og + ((size_t)(b * SEQ) + row0) * DIMC + h * HDIM + (lane & 3) * 2;
    #pragma unroll
    for (int dt = 0; dt < 8; dt++) {
        *(__nv_bfloat162*)(out0 + dt * 8) =
            __floats2bfloat162_rn(o[dt][0] * linv0, o[dt][1] * linv0);
        *(__nv_bfloat162*)(out0 + 8 * DIMC + dt * 8) =
            __floats2bfloat162_rn(o[dt][2] * linv1, o[dt][3] * linv1);
    }
}

// ---------------- launch ----------------
extern "C" void kernel_launch(void* const* d_in, const int* in_sizes, int n_in,
                              void* d_out, int out_size)
{
    const float* x      = (const float*)d_in[0];
    const float* qkv_w  = (const float*)d_in[1];
    const float* qkv_b  = (const float*)d_in[2];
    const float* proj_w = (const float*)d_in[3];
    const float* proj_b = (const float*)d_in[4];
    const float* fc1_w  = (const float*)d_in[5];
    const float* fc1_b  = (const float*)d_in[6];
    const float* eye1_w = (const float*)d_in[7];
    const float* eye2_w = (const float*)d_in[8];
    const float* fc2_w  = (const float*)d_in[9];
    const float* fc2_b  = (const float*)d_in[10];
    const float* n1w    = (const float*)d_in[11];
    const float* n1b    = (const float*)d_in[12];
    const float* n2w    = (const float*)d_in[13];
    const float* n2b    = (const float*)d_in[14];
    const float* ls1    = (const float*)d_in[15];
    const float* ls2    = (const float*)d_in[16];
    float* out = (float*)d_out;

    __nv_bfloat16 *hb, *qkvb, *ob, *ab, *wqkv, *wproj, *wfc2;
    uint8_t *h8, *a8, *b8, *wfc1_8, *weye1_8, *weye2_8;
    cudaGetSymbolAddress((void**)&hb,   g_hb);
    cudaGetSymbolAddress((void**)&h8,   g_h8);
    cudaGetSymbolAddress((void**)&qkvb, g_qkvb);
    cudaGetSymbolAddress((void**)&ob,   g_ob);
    cudaGetSymbolAddress((void**)&a8,   g_a8);
    cudaGetSymbolAddress((void**)&b8,   g_b8);
    cudaGetSymbolAddress((void**)&ab,   g_ab);
    cudaGetSymbolAddress((void**)&wqkv,    g_wqkv);
    cudaGetSymbolAddress((void**)&wproj,   g_wproj);
    cudaGetSymbolAddress((void**)&wfc2,    g_wfc2);
    cudaGetSymbolAddress((void**)&wfc1_8,  g_wfc1_8);
    cudaGetSymbolAddress((void**)&weye1_8, g_weye1_8);
    cudaGetSymbolAddress((void**)&weye2_8, g_weye2_8);

    cudaFuncSetAttribute(attn_bf16, cudaFuncAttributeMaxDynamicSharedMemorySize, ATTN_SMEM);

    const int CT = 256;
    const dim3 blk(256);

    // 0: convert qkv weights (needed by launch 2)
    f2bf_kernel<<<(QKV3 * DIMC / 4 + CT - 1) / CT, CT>>>(qkv_w,  wqkv,  QKV3 * DIMC);
    // 1: h = LN1(x) -> bf16
    ln_kernel<0><<<NTOK, 128>>>(x, n1w, n1b, hb);
    // 2: qkv = h @ qkv_w^T + qkv_b -> bf16
    gemm_bf16<0, 1><<<dim3(QKV3 / 128, NTOK / 128), blk>>>(hb, wqkv, qkv_b, nullptr, nullptr, qkvb, QKV3, DIMC);
    // 3: o = attention(qkv)   <-- PROFILED (4th launch)
    attn_bf16<<<dim3(SEQ / 128, HEADS, BATCH), 256, ATTN_SMEM>>>(qkvb, ob);

    // remaining weight converts
    f2bf_kernel<<<(DIMC * DIMC / 4 + CT - 1) / CT, CT>>>(proj_w, wproj, DIMC * DIMC);
    f2bf_kernel<<<(DIMC * HID / 4 + CT - 1) / CT, CT>>>(fc2_w,  wfc2,  DIMC * HID);
    f2f8_kernel<<<(HID * DIMC / 4 + CT - 1) / CT, CT>>>(fc1_w,  wfc1_8,  HID * DIMC);
    f2f8_kernel<<<(HID * HID / 4 + CT - 1) / CT, CT>>>(eye1_w, weye1_8, HID * HID);
    f2f8_kernel<<<(HID * HID / 4 + CT - 1) / CT, CT>>>(eye2_w, weye2_8, HID * HID);

    // out = x + (o @ proj_w^T + proj_b) * ls1 -> fp32
    gemm_bf16<2, 0><<<dim3(DIMC / 128, NTOK / 128), blk>>>(ob, wproj, proj_b, x, ls1, out, DIMC, DIMC);
    // h8 = LN2(out) -> fp8
    ln_kernel<1><<<NTOK, 128>>>(out, n2w, n2b, h8);
    // a8 = gelu(h8 @ fc1_w^T + fc1_b) -> fp8
    gemm_fp8<1, 1><<<dim3(HID / 128, NTOK / 128), blk>>>(h8, wfc1_8, fc1_b, a8, HID, DIMC);
    // b8 = a8 @ eye1_w^T -> fp8
    gemm_fp8<0, 1><<<dim3(HID / 128, NTOK / 128), blk>>>(a8, weye1_8, nullptr, b8, HID, HID);
    // ab = b8 @ eye2_w^T -> bf16
    gemm_fp8<0, 0><<<dim3(HID / 128, NTOK / 128), blk>>>(b8, weye2_8, nullptr, ab, HID, HID);
    // out = out + (ab @ fc2_w^T + fc2_b) * ls2 -> fp32
    gemm_bf16<2, 0><<<dim3(DIMC / 128, NTOK / 128), blk>>>(ab, wfc2, fc2_b, out, ls2, out, DIMC, HID);
}

// round 9
// speedup vs baseline: 1.7970x; 1.7942x over previous
#include <cuda_runtime.h>
#include <cuda_bf16.h>
#include <math.h>
#include <stdint.h>

// ---------------- problem constants ----------------
#define NTOK 16384      // 8 * 2048 tokens
#define SEQ  2048
#define BATCH 8
#define DIMC 384
#define QKV3 1152
#define HID  1536
#define HEADS 6
#define HDIM 64
#define EPSV 1e-5f

// ---------------- scratch (device globals) ----------------
__device__ __nv_bfloat16 g_hb  [(size_t)NTOK * DIMC];   // LN out (bf16)
__device__ __nv_bfloat16 g_qkvb[(size_t)NTOK * QKV3];
__device__ __nv_bfloat16 g_ob  [(size_t)NTOK * DIMC];
__device__ __nv_bfloat16 g_ab  [(size_t)NTOK * HID];    // fc1 out (bf16)
__device__ __nv_bfloat16 g_wqkv [(size_t)QKV3 * DIMC];
__device__ __nv_bfloat16 g_wproj[(size_t)DIMC * DIMC];
__device__ __nv_bfloat16 g_wfc1 [(size_t)HID * DIMC];
__device__ __nv_bfloat16 g_wfc2 [(size_t)DIMC * HID];
__device__ __nv_bfloat16 g_weye1[(size_t)HID * HID];
__device__ __nv_bfloat16 g_weye2[(size_t)HID * HID];
__device__ __nv_bfloat16 g_U    [(size_t)DIMC * HID];   // fc2 @ eye2
__device__ __nv_bfloat16 g_Wbig [(size_t)DIMC * HID];   // (fc2 @ eye2) @ eye1

// ---------------- helpers ----------------
__device__ __forceinline__ uint32_t smem_u32(const void* p) {
    return (uint32_t)__cvta_generic_to_shared(p);
}
__device__ __forceinline__ void cp16u(uint32_t dst, const void* src) {
    asm volatile("cp.async.cg.shared.global [%0],[%1],16;\n" :: "r"(dst), "l"(src));
}
__device__ __forceinline__ void cp_commit() { asm volatile("cp.async.commit_group;\n"); }
template<int N>
__device__ __forceinline__ void cp_wait() { asm volatile("cp.async.wait_group %0;\n" :: "n"(N)); }
__device__ __forceinline__ void ldm_x4(uint32_t& r0, uint32_t& r1, uint32_t& r2, uint32_t& r3, uint32_t a) {
    asm volatile("ldmatrix.sync.aligned.m8n8.x4.shared.b16 {%0,%1,%2,%3},[%4];\n"
                 : "=r"(r0), "=r"(r1), "=r"(r2), "=r"(r3) : "r"(a));
}
__device__ __forceinline__ void ldm_x4_t(uint32_t& r0, uint32_t& r1, uint32_t& r2, uint32_t& r3, uint32_t a) {
    asm volatile("ldmatrix.sync.aligned.m8n8.x4.trans.shared.b16 {%0,%1,%2,%3},[%4];\n"
                 : "=r"(r0), "=r"(r1), "=r"(r2), "=r"(r3) : "r"(a));
}
__device__ __forceinline__ void mma_bf16(float c[4], const uint32_t a[4], const uint32_t b[2]) {
    asm volatile(
        "mma.sync.aligned.m16n8k16.row.col.f32.bf16.bf16.f32 "
        "{%0,%1,%2,%3},{%4,%5,%6,%7},{%8,%9},{%0,%1,%2,%3};\n"
        : "+f"(c[0]), "+f"(c[1]), "+f"(c[2]), "+f"(c[3])
        : "r"(a[0]), "r"(a[1]), "r"(a[2]), "r"(a[3]), "r"(b[0]), "r"(b[1]));
}
__device__ __forceinline__ uint32_t packbf(float lo, float hi) {
    __nv_bfloat162 h = __floats2bfloat162_rn(lo, hi);
    return *reinterpret_cast<uint32_t*>(&h);
}
__device__ __forceinline__ float gelu_exact(float x) {
    return 0.5f * x * (1.0f + erff(x * 0.7071067811865475f));
}

// ---------------- fp32 -> bf16 convert ----------------
__global__ void f2bf_kernel(const float* __restrict__ in, __nv_bfloat16* __restrict__ out, int n) {
    int i = (blockIdx.x * blockDim.x + threadIdx.x) * 4;
    if (i < n) {
        float4 v = *(const float4*)(in + i);
        *(__nv_bfloat162*)(out + i)     = __floats2bfloat162_rn(v.x, v.y);
        *(__nv_bfloat162*)(out + i + 2) = __floats2bfloat162_rn(v.z, v.w);
    }
}

// ---------------- LayerNorm -> bf16 ----------------
__global__ void ln_kernel(const float* __restrict__ x, const float* __restrict__ w,
                          const float* __restrict__ b, __nv_bfloat16* __restrict__ out)
{
    const int t = blockIdx.x;
    const float* xr = x + (size_t)t * DIMC;
    __nv_bfloat16* orow = out + (size_t)t * DIMC;
    const int tid = threadIdx.x;

    float v0 = xr[tid], v1 = xr[tid + 128], v2 = xr[tid + 256];
    float s = v0 + v1 + v2;
    float q = v0 * v0 + v1 * v1 + v2 * v2;
    #pragma unroll
    for (int off = 16; off > 0; off >>= 1) {
        s += __shfl_xor_sync(0xffffffffu, s, off);
        q += __shfl_xor_sync(0xffffffffu, q, off);
    }
    __shared__ float ss[4], qq[4];
    if ((tid & 31) == 0) { ss[tid >> 5] = s; qq[tid >> 5] = q; }
    __syncthreads();
    s = ss[0] + ss[1] + ss[2] + ss[3];
    q = qq[0] + qq[1] + qq[2] + qq[3];
    const float mean = s * (1.0f / DIMC);
    const float var  = q * (1.0f / DIMC) - mean * mean;
    const float inv  = rsqrtf(var + EPSV);

    orow[tid]       = __float2bfloat16((v0 - mean) * inv * w[tid]       + b[tid]);
    orow[tid + 128] = __float2bfloat16((v1 - mean) * inv * w[tid + 128] + b[tid + 128]);
    orow[tid + 256] = __float2bfloat16((v2 - mean) * inv * w[tid + 256] + b[tid + 256]);
}

// ---------------- bf16 NT GEMM 128x128: C = epi(A @ W^T) (round-2 proven) ----------------
#define GP 40
template<int MODE, int OUTBF>
__global__ void __launch_bounds__(256) gemm_bf16(
    const __nv_bfloat16* __restrict__ A, const __nv_bfloat16* __restrict__ W,
    const float* __restrict__ bias, const float* __restrict__ res,
    const float* __restrict__ gamma, void* __restrict__ Cout,
    int N, int K)
{
    __shared__ __align__(16) __nv_bfloat16 sA[2][128 * GP];
    __shared__ __align__(16) __nv_bfloat16 sB[2][128 * GP];

    const int tid  = threadIdx.x;
    const int lane = tid & 31;
    const int warp = tid >> 5;
    const int wm = warp >> 1;
    const int wn = warp & 1;
    const size_t bm = (size_t)blockIdx.y * 128;
    const size_t bn = (size_t)blockIdx.x * 128;

    const __nv_bfloat16* Ab = A + bm * (size_t)K;
    const __nv_bfloat16* Wb = W + bn * (size_t)K;

    float c[2][8][4];
    #pragma unroll
    for (int i = 0; i < 2; i++)
        #pragma unroll
        for (int j = 0; j < 8; j++)
            #pragma unroll
            for (int k = 0; k < 4; k++) c[i][j][k] = 0.0f;

    const int lrow = tid >> 2;
    const int loff = (tid & 3) * 8;

    uint4 a0v, a1v, b0v, b1v;
    a0v = *(const uint4*)(Ab + (size_t)lrow * K + loff);
    a1v = *(const uint4*)(Ab + (size_t)(lrow + 64) * K + loff);
    b0v = *(const uint4*)(Wb + (size_t)lrow * K + loff);
    b1v = *(const uint4*)(Wb + (size_t)(lrow + 64) * K + loff);
    *(uint4*)(&sA[0][lrow * GP + loff])        = a0v;
    *(uint4*)(&sA[0][(lrow + 64) * GP + loff]) = a1v;
    *(uint4*)(&sB[0][lrow * GP + loff])        = b0v;
    *(uint4*)(&sB[0][(lrow + 64) * GP + loff]) = b1v;
    __syncthreads();

    const int nk = K >> 5;
    int buf = 0;
    for (int t = 0; t < nk; t++) {
        if (t + 1 < nk) {
            const int kt = (t + 1) << 5;
            a0v = *(const uint4*)(Ab + (size_t)lrow * K + kt + loff);
            a1v = *(const uint4*)(Ab + (size_t)(lrow + 64) * K + kt + loff);
            b0v = *(const uint4*)(Wb + (size_t)lrow * K + kt + loff);
            b1v = *(const uint4*)(Wb + (size_t)(lrow + 64) * K + kt + loff);
        }
        const uint32_t abase = smem_u32(&sA[buf][0]);
        const uint32_t bbase = smem_u32(&sB[buf][0]);
        #pragma unroll
        for (int kk = 0; kk < 2; kk++) {
            uint32_t af[2][4];
            #pragma unroll
            for (int mt = 0; mt < 2; mt++) {
                uint32_t addr = abase +
                    (((wm * 32 + mt * 16 + (lane & 15)) * GP) + kk * 16 + ((lane >> 4) << 3)) * 2;
                ldm_x4(af[mt][0], af[mt][1], af[mt][2], af[mt][3], addr);
            }
            uint32_t bfv[8][2];
            #pragma unroll
            for (int p = 0; p < 4; p++) {
                uint32_t addr = bbase +
                    (((wn * 64 + p * 16 + ((lane >> 4) << 3) + (lane & 7)) * GP) +
                     kk * 16 + (((lane >> 3) & 1) << 3)) * 2;
                ldm_x4(bfv[2 * p][0], bfv[2 * p][1], bfv[2 * p + 1][0], bfv[2 * p + 1][1], addr);
            }
            #pragma unroll
            for (int mt = 0; mt < 2; mt++)
                #pragma unroll
                for (int nt = 0; nt < 8; nt++)
                    mma_bf16(c[mt][nt], af[mt], bfv[nt]);
        }
        if (t + 1 < nk) {
            const int nb = buf ^ 1;
            *(uint4*)(&sA[nb][lrow * GP + loff])        = a0v;
            *(uint4*)(&sA[nb][(lrow + 64) * GP + loff]) = a1v;
            *(uint4*)(&sB[nb][lrow * GP + loff])        = b0v;
            *(uint4*)(&sB[nb][(lrow + 64) * GP + loff]) = b1v;
        }
        __syncthreads();
        buf ^= 1;
    }

    const int r = lane >> 2;
    const int c2 = (lane & 3) * 2;
    #pragma unroll
    for (int mt = 0; mt < 2; mt++) {
        const size_t row0 = bm + wm * 32 + mt * 16 + r;
        const size_t row1 = row0 + 8;
        #pragma unroll
        for (int nt = 0; nt < 8; nt++) {
            const int col = (int)bn + wn * 64 + nt * 8 + c2;
            float b0 = 0.f, b1 = 0.f;
            if (MODE != 0 || bias) { b0 = bias[col]; b1 = bias[col + 1]; }
            float v00 = c[mt][nt][0] + b0, v01 = c[mt][nt][1] + b1;
            float v10 = c[mt][nt][2] + b0, v11 = c[mt][nt][3] + b1;
            if (MODE == 1) {
                v00 = gelu_exact(v00); v01 = gelu_exact(v01);
                v10 = gelu_exact(v10); v11 = gelu_exact(v11);
            } else if (MODE == 2) {
                const float g0 = gamma[col], g1 = gamma[col + 1];
                v00 = res[row0 * N + col] + v00 * g0;
                v01 = res[row0 * N + col + 1] + v01 * g1;
                v10 = res[row1 * N + col] + v10 * g0;
                v11 = res[row1 * N + col + 1] + v11 * g1;
            }
            if (OUTBF) {
                __nv_bfloat16* C = (__nv_bfloat16*)Cout;
                *(__nv_bfloat162*)(C + row0 * N + col) = __floats2bfloat162_rn(v00, v01);
                *(__nv_bfloat162*)(C + row1 * N + col) = __floats2bfloat162_rn(v10, v11);
            } else {
                float* C = (float*)Cout;
                *(float2*)(C + row0 * N + col) = make_float2(v00, v01);
                *(float2*)(C + row1 * N + col) = make_float2(v10, v11);
            }
        }
    }
}

// ---------------- bf16 NN GEMM 128x128: C = A @ B  (B row-major [K,N]) ----------------
// Weight-folding only (small M). B tile stored k-major in SMEM; fragments via
// ldmatrix.trans — exact addressing pattern proven in the attention PV stage.
#define BP 136   // 128 data + 8 pad halves
__global__ void __launch_bounds__(256) gemm_nn_bf16(
    const __nv_bfloat16* __restrict__ A, const __nv_bfloat16* __restrict__ B,
    __nv_bfloat16* __restrict__ C, int N, int K)
{
    __shared__ __align__(16) __nv_bfloat16 sA[2][128 * GP];
    __shared__ __align__(16) __nv_bfloat16 sB[2][32 * BP];

    const int tid  = threadIdx.x;
    const int lane = tid & 31;
    const int warp = tid >> 5;
    const int wm = warp >> 1;
    const int wn = warp & 1;
    const size_t bm = (size_t)blockIdx.y * 128;
    const size_t bn = (size_t)blockIdx.x * 128;

    const __nv_bfloat16* Ab = A + bm * (size_t)K;

    float c[2][8][4];
    #pragma unroll
    for (int i = 0; i < 2; i++)
        #pragma unroll
        for (int j = 0; j < 8; j++)
            #pragma unroll
            for (int k = 0; k < 4; k++) c[i][j][k] = 0.0f;

    const int lrow = tid >> 2;          // 0..63 (A rows)
    const int loff = (tid & 3) * 8;
    const int brow = tid >> 4;          // 0..15 (B k-rows)
    const int bcol = (tid & 15) * 8;    // 0..120

    uint4 a0v, a1v, b0v, b1v;
    a0v = *(const uint4*)(Ab + (size_t)lrow * K + loff);
    a1v = *(const uint4*)(Ab + (size_t)(lrow + 64) * K + loff);
    b0v = *(const uint4*)(B + (size_t)brow * N + bn + bcol);
    b1v = *(const uint4*)(B + (size_t)(brow + 16) * N + bn + bcol);
    *(uint4*)(&sA[0][lrow * GP + loff])        = a0v;
    *(uint4*)(&sA[0][(lrow + 64) * GP + loff]) = a1v;
    *(uint4*)(&sB[0][brow * BP + bcol])        = b0v;
    *(uint4*)(&sB[0][(brow + 16) * BP + bcol]) = b1v;
    __syncthreads();

    const int nk = K >> 5;
    int buf = 0;
    for (int t = 0; t < nk; t++) {
        if (t + 1 < nk) {
            const int kt = (t + 1) << 5;
            a0v = *(const uint4*)(Ab + (size_t)lrow * K + kt + loff);
            a1v = *(const uint4*)(Ab + (size_t)(lrow + 64) * K + kt + loff);
            b0v = *(const uint4*)(B + (size_t)(kt + brow) * N + bn + bcol);
            b1v = *(const uint4*)(B + (size_t)(kt + brow + 16) * N + bn + bcol);
        }
        const uint32_t abase = smem_u32(&sA[buf][0]);
        const uint32_t bbase = smem_u32(&sB[buf][0]);
        #pragma unroll
        for (int kk = 0; kk < 2; kk++) {
            uint32_t af[2][4];
            #pragma unroll
            for (int mt = 0; mt < 2; mt++) {
                uint32_t addr = abase +
                    (((wm * 32 + mt * 16 + (lane & 15)) * GP) + kk * 16 + ((lane >> 4) << 3)) * 2;
                ldm_x4(af[mt][0], af[mt][1], af[mt][2], af[mt][3], addr);
            }
            uint32_t bfv[8][2];
            #pragma unroll
            for (int p = 0; p < 4; p++) {
                uint32_t addr = bbase +
                    (((kk * 16 + (lane & 7) + (((lane >> 3) & 1) << 3)) * BP) +
                     wn * 64 + p * 16 + ((lane >> 4) << 3)) * 2;
                ldm_x4_t(bfv[2 * p][0], bfv[2 * p][1], bfv[2 * p + 1][0], bfv[2 * p + 1][1], addr);
            }
            #pragma unroll
            for (int mt = 0; mt < 2; mt++)
                #pragma unroll
                for (int nt = 0; nt < 8; nt++)
                    mma_bf16(c[mt][nt], af[mt], bfv[nt]);
        }
        if (t + 1 < nk) {
            const int nb = buf ^ 1;
            *(uint4*)(&sA[nb][lrow * GP + loff])        = a0v;
            *(uint4*)(&sA[nb][(lrow + 64) * GP + loff]) = a1v;
            *(uint4*)(&sB[nb][brow * BP + bcol])        = b0v;
            *(uint4*)(&sB[nb][(brow + 16) * BP + bcol]) = b1v;
        }
        __syncthreads();
        buf ^= 1;
    }

    const int r = lane >> 2;
    const int c2 = (lane & 3) * 2;
    #pragma unroll
    for (int mt = 0; mt < 2; mt++) {
        const size_t row0 = bm + wm * 32 + mt * 16 + r;
        const size_t row1 = row0 + 8;
        #pragma unroll
        for (int nt = 0; nt < 8; nt++) {
            const int col = (int)bn + wn * 64 + nt * 8 + c2;
            *(__nv_bfloat162*)(C + row0 * N + col) = __floats2bfloat162_rn(c[mt][nt][0], c[mt][nt][1]);
            *(__nv_bfloat162*)(C + row1 * N + col) = __floats2bfloat162_rn(c[mt][nt][2], c[mt][nt][3]);
        }
    }
}

// ---------------- bf16 flash attention: Q 128x64, 256 threads, cp.async KV pipeline ----------------
#define AQP 72
#define ATTN_SMEM ((128 * AQP + 4 * 64 * AQP) * (int)sizeof(__nv_bfloat16))
__global__ void __launch_bounds__(256) attn_bf16(const __nv_bfloat16* __restrict__ qkv,
                                                 __nv_bfloat16* __restrict__ og)
{
    extern __shared__ __align__(16) __nv_bfloat16 asm_[];
    __nv_bfloat16* Qs = asm_;                       // [128][AQP]
    __nv_bfloat16* Ks = Qs + 128 * AQP;             // [2][64][AQP]
    __nv_bfloat16* Vs = Ks + 2 * 64 * AQP;          // [2][64][AQP]

    const int b  = blockIdx.z;
    const int h  = blockIdx.y;
    const int qt = blockIdx.x;
    const int tid  = threadIdx.x;
    const int lane = tid & 31;
    const int warp = tid >> 5;
    const size_t base = (size_t)b * SEQ * QKV3;

    #pragma unroll
    for (int i = 0; i < 4; i++) {
        const int cidx = tid + i * 256;
        const int row = cidx >> 3;
        const int off = (cidx & 7) * 8;
        *(uint4*)(Qs + row * AQP + off) =
            *(const uint4*)(qkv + base + (size_t)(qt * 128 + row) * QKV3 + h * HDIM + off);
    }

    auto load_kv = [&](int kt, int s) {
        __nv_bfloat16* Kd = Ks + s * 64 * AQP;
        __nv_bfloat16* Vd = Vs + s * 64 * AQP;
        #pragma unroll
        for (int i = 0; i < 2; i++) {
            const int cidx = tid + i * 256;
            const int row = cidx >> 3;
            const int off = (cidx & 7) * 8;
            const __nv_bfloat16* g = qkv + base + (size_t)(kt * 64 + row) * QKV3 + h * HDIM + off;
            cp16u(smem_u32(Kd + row * AQP + off), g + DIMC);
            cp16u(smem_u32(Vd + row * AQP + off), g + 2 * DIMC);
        }
    };

    float m_run[2] = { -1e30f, -1e30f };
    float l_run[2] = { 0.0f, 0.0f };
    float o[8][4];
    #pragma unroll
    for (int i = 0; i < 8; i++)
        #pragma unroll
        for (int j = 0; j < 4; j++) o[i][j] = 0.0f;

    const uint32_t qb = smem_u32(Qs);

    load_kv(0, 0);
    cp_commit();

    int buf = 0;
    for (int kt = 0; kt < 32; kt++) {
        if (kt + 1 < 32) load_kv(kt + 1, buf ^ 1);
        cp_commit();
        cp_wait<1>();
        __syncthreads();

        const uint32_t kb = smem_u32(Ks + buf * 64 * AQP);
        const uint32_t vb = smem_u32(Vs + buf * 64 * AQP);

        float s[8][4];
        #pragma unroll
        for (int i = 0; i < 8; i++)
            #pragma unroll
            for (int j = 0; j < 4; j++) s[i][j] = 0.0f;

        #pragma unroll
        for (int ks = 0; ks < 4; ks++) {
            uint32_t a[4];
            uint32_t aaddr = qb + (((warp * 16 + (lane & 15)) * AQP) + ks * 16 + ((lane >> 4) << 3)) * 2;
            ldm_x4(a[0], a[1], a[2], a[3], aaddr);
            uint32_t bbv[8][2];
            #pragma unroll
            for (int p = 0; p < 4; p++) {
                uint32_t baddr = kb + (((p * 16 + ((lane >> 4) << 3) + (lane & 7)) * AQP) +
                                       ks * 16 + (((lane >> 3) & 1) << 3)) * 2;
                ldm_x4(bbv[2 * p][0], bbv[2 * p][1], bbv[2 * p + 1][0], bbv[2 * p + 1][1], baddr);
            }
            #pragma unroll
            for (int nt = 0; nt < 8; nt++) mma_bf16(s[nt], a, bbv[nt]);
        }

        #pragma unroll
        for (int rr = 0; rr < 2; rr++) {
            float rmax = s[0][rr * 2];
            #pragma unroll
            for (int nt = 0; nt < 8; nt++) {
                rmax = fmaxf(rmax, s[nt][rr * 2]);
                rmax = fmaxf(rmax, s[nt][rr * 2 + 1]);
            }
            rmax = fmaxf(rmax, __shfl_xor_sync(0xffffffffu, rmax, 1));
            rmax = fmaxf(rmax, __shfl_xor_sync(0xffffffffu, rmax, 2));
            const float mn = fmaxf(m_run[rr], rmax * 0.125f);
            const float corr = __expf(m_run[rr] - mn);
            m_run[rr] = mn;
            float rs = 0.0f;
            #pragma unroll
            for (int nt = 0; nt < 8; nt++) {
                float p0 = __expf(s[nt][rr * 2] * 0.125f - mn);
                float p1 = __expf(s[nt][rr * 2 + 1] * 0.125f - mn);
                s[nt][rr * 2] = p0; s[nt][rr * 2 + 1] = p1;
                rs += p0 + p1;
            }
            rs += __shfl_xor_sync(0xffffffffu, rs, 1);
            rs += __shfl_xor_sync(0xffffffffu, rs, 2);
            l_run[rr] = l_run[rr] * corr + rs;
            #pragma unroll
            for (int dt = 0; dt < 8; dt++) {
                o[dt][rr * 2] *= corr;
                o[dt][rr * 2 + 1] *= corr;
            }
        }

        #pragma unroll
        for (int j = 0; j < 4; j++) {
            uint32_t aP[4];
            aP[0] = packbf(s[2 * j][0], s[2 * j][1]);
            aP[1] = packbf(s[2 * j][2], s[2 * j][3]);
            aP[2] = packbf(s[2 * j + 1][0], s[2 * j + 1][1]);
            aP[3] = packbf(s[2 * j + 1][2], s[2 * j + 1][3]);
            uint32_t bv[8][2];
            #pragma unroll
            for (int p = 0; p < 4; p++) {
                uint32_t baddr = vb + (((j * 16 + (lane & 7) + (((lane >> 3) & 1) << 3)) * AQP) +
                                       p * 16 + ((lane >> 4) << 3)) * 2;
                ldm_x4_t(bv[2 * p][0], bv[2 * p][1], bv[2 * p + 1][0], bv[2 * p + 1][1], baddr);
            }
            #pragma unroll
            for (int dt = 0; dt < 8; dt++) mma_bf16(o[dt], aP, bv[dt]);
        }
        __syncthreads();
        buf ^= 1;
    }

    const float linv0 = 1.0f / l_run[0];
    const float linv1 = 1.0f / l_run[1];
    const int row0 = qt * 128 + warp * 16 + (lane >> 2);
    __nv_bfloat16* out0 = og + ((size_t)(b * SEQ) + row0) * DIMC + h * HDIM + (lane & 3) * 2;
    #pragma unroll
    for (int dt = 0; dt < 8; dt++) {
        *(__nv_bfloat162*)(out0 + dt * 8) =
            __floats2bfloat162_rn(o[dt][0] * linv0, o[dt][1] * linv0);
        *(__nv_bfloat162*)(out0 + 8 * DIMC + dt * 8) =
            __floats2bfloat162_rn(o[dt][2] * linv1, o[dt][3] * linv1);
    }
}

// ---------------- launch ----------------
extern "C" void kernel_launch(void* const* d_in, const int* in_sizes, int n_in,
                              void* d_out, int out_size)
{
    const float* x      = (const float*)d_in[0];
    const float* qkv_w  = (const float*)d_in[1];
    const float* qkv_b  = (const float*)d_in[2];
    const float* proj_w = (const float*)d_in[3];
    const float* proj_b = (const float*)d_in[4];
    const float* fc1_w  = (const float*)d_in[5];
    const float* fc1_b  = (const float*)d_in[6];
    const float* eye1_w = (const float*)d_in[7];
    const float* eye2_w = (const float*)d_in[8];
    const float* fc2_w  = (const float*)d_in[9];
    const float* fc2_b  = (const float*)d_in[10];
    const float* n1w    = (const float*)d_in[11];
    const float* n1b    = (const float*)d_in[12];
    const float* n2w    = (const float*)d_in[13];
    const float* n2b    = (const float*)d_in[14];
    const float* ls1    = (const float*)d_in[15];
    const float* ls2    = (const float*)d_in[16];
    float* out = (float*)d_out;

    __nv_bfloat16 *hb, *qkvb, *ob, *ab;
    __nv_bfloat16 *wqkv, *wproj, *wfc1, *wfc2, *weye1, *weye2, *U, *Wbig;
    cudaGetSymbolAddress((void**)&hb,   g_hb);
    cudaGetSymbolAddress((void**)&qkvb, g_qkvb);
    cudaGetSymbolAddress((void**)&ob,   g_ob);
    cudaGetSymbolAddress((void**)&ab,   g_ab);
    cudaGetSymbolAddress((void**)&wqkv,  g_wqkv);
    cudaGetSymbolAddress((void**)&wproj, g_wproj);
    cudaGetSymbolAddress((void**)&wfc1,  g_wfc1);
    cudaGetSymbolAddress((void**)&wfc2,  g_wfc2);
    cudaGetSymbolAddress((void**)&weye1, g_weye1);
    cudaGetSymbolAddress((void**)&weye2, g_weye2);
    cudaGetSymbolAddress((void**)&U,     g_U);
    cudaGetSymbolAddress((void**)&Wbig,  g_Wbig);

    cudaFuncSetAttribute(attn_bf16, cudaFuncAttributeMaxDynamicSharedMemorySize, ATTN_SMEM);

    const int CT = 256;
    const dim3 blk(256);

    // 0: convert qkv weights (needed by launch 2)
    f2bf_kernel<<<(QKV3 * DIMC / 4 + CT - 1) / CT, CT>>>(qkv_w,  wqkv,  QKV3 * DIMC);
    // 1: h = LN1(x) -> bf16
    ln_kernel<<<NTOK, 128>>>(x, n1w, n1b, hb);
    // 2: qkv = h @ qkv_w^T + qkv_b -> bf16
    gemm_bf16<0, 1><<<dim3(QKV3 / 128, NTOK / 128), blk>>>(hb, wqkv, qkv_b, nullptr, nullptr, qkvb, QKV3, DIMC);
    // 3: o = attention(qkv)   <-- PROFILED (4th launch)
    attn_bf16<<<dim3(SEQ / 128, HEADS, BATCH), 256, ATTN_SMEM>>>(qkvb, ob);

    // remaining weight converts
    f2bf_kernel<<<(DIMC * DIMC / 4 + CT - 1) / CT, CT>>>(proj_w, wproj, DIMC * DIMC);
    f2bf_kernel<<<(HID * DIMC / 4 + CT - 1) / CT, CT>>>(fc1_w,  wfc1,  HID * DIMC);
    f2bf_kernel<<<(DIMC * HID / 4 + CT - 1) / CT, CT>>>(fc2_w,  wfc2,  DIMC * HID);
    f2bf_kernel<<<(HID * HID / 4 + CT - 1) / CT, CT>>>(eye1_w, weye1, HID * HID);
    f2bf_kernel<<<(HID * HID / 4 + CT - 1) / CT, CT>>>(eye2_w, weye2, HID * HID);

    // weight folding: Wbig = fc2 @ eye2 @ eye1  (384x1536, tiny GEMMs)
    gemm_nn_bf16<<<dim3(HID / 128, DIMC / 128), blk>>>(wfc2, weye2, U,    HID, HID);
    gemm_nn_bf16<<<dim3(HID / 128, DIMC / 128), blk>>>(U,    weye1, Wbig, HID, HID);

    // out = x + (o @ proj_w^T + proj_b) * ls1 -> fp32
    gemm_bf16<2, 0><<<dim3(DIMC / 128, NTOK / 128), blk>>>(ob, wproj, proj_b, x, ls1, out, DIMC, DIMC);
    // h = LN2(out) -> bf16
    ln_kernel<<<NTOK, 128>>>(out, n2w, n2b, hb);
    // ab = gelu(h @ fc1_w^T + fc1_b) -> bf16
    gemm_bf16<1, 1><<<dim3(HID / 128, NTOK / 128), blk>>>(hb, wfc1, fc1_b, nullptr, nullptr, ab, HID, DIMC);
    // out = out + (ab @ Wbig^T + fc2_b) * ls2 -> fp32   (eye1/eye2 folded into Wbig)
    gemm_bf16<2, 0><<<dim3(DIMC / 128, NTOK / 128), blk>>>(ab, Wbig, fc2_b, out, ls2, out, DIMC, HID);
}